// round 3
// baseline (speedup 1.0000x reference)
#include <cuda_runtime.h>

#define NN 50000
#define EE 1600000
#define GG 16
#define HH 128
#define HOPS 3

// ---------------- scratch (static device memory; no allocations) ----------------
__device__ float d_emb_a[NN * HH];
__device__ float d_emb_b[NN * HH];
__device__ float d_aggr[NN * HH];   // ne_aggr, then reused as z = emb @ W7^T
__device__ float d_dw[NN];          // sum of edge_attr per destination (row)
__device__ int   d_counts[NN];
__device__ int   d_rowptr[NN + 1];
__device__ int   d_cursor[NN];
__device__ int   d_col[EE];
__device__ float d_v3[HOPS * HH];       // v3[l][h'] = sum_h W3[l][h',h] * relu(W4[l][h])
__device__ float d_W2T[HOPS * HH * HH]; // W2T[l][k][h'] = W2[l][h'][k]
__device__ float d_W7T[HH * HH];        // W7T[k][h'] = W7[h'][k]
__device__ float d_pooled[GG * HH];
__device__ float d_tg[GG];

// ---------------- zero the per-launch accumulators ----------------
__global__ void k_zero() {
    int i = blockIdx.x * blockDim.x + threadIdx.x;
    int stride = gridDim.x * blockDim.x;
    for (int j = i; j < NN; j += stride) {
        d_dw[j] = 0.f;
        d_counts[j] = 0;
        d_cursor[j] = 0;
    }
    if (i < GG * HH) d_pooled[i] = 0.f;
}

// ---------------- edge pass 1: degree histogram + weighted degree ----------------
__global__ void k_edge1(const int* __restrict__ ei, const float* __restrict__ ea) {
    int e = blockIdx.x * blockDim.x + threadIdx.x;
    if (e >= EE) return;
    int r = ei[e];               // row (destination of aggregation)
    if (r < 0 || r >= NN) return;
    atomicAdd(&d_counts[r], 1);
    atomicAdd(&d_dw[r], ea[e]);
}

// ---------------- single-block exclusive scan over counts -> rowptr ----------------
__global__ void k_scan() {
    __shared__ int sm[1024];
    int tid = threadIdx.x;
    const int CH = (NN + 1023) / 1024;  // 49
    int base = tid * CH;
    int s = 0;
    for (int j = 0; j < CH; j++) {
        int idx = base + j;
        if (idx < NN) s += d_counts[idx];
    }
    sm[tid] = s;
    __syncthreads();
    for (int off = 1; off < 1024; off <<= 1) {
        int v = (tid >= off) ? sm[tid - off] : 0;
        __syncthreads();
        sm[tid] += v;
        __syncthreads();
    }
    int run = (tid == 0) ? 0 : sm[tid - 1];
    for (int j = 0; j < CH; j++) {
        int idx = base + j;
        if (idx < NN) {
            d_rowptr[idx] = run;
            run += d_counts[idx];
        }
    }
    if (tid == 1023) d_rowptr[NN] = sm[1023];
}

// ---------------- edge pass 2: scatter cols into CSR ----------------
__global__ void k_edge2(const int* __restrict__ ei) {
    int e = blockIdx.x * blockDim.x + threadIdx.x;
    if (e >= EE) return;
    int r = ei[e];
    int c = ei[EE + e];
    if (r < 0 || r >= NN) return;
    if (c < 0) c = 0;
    if (c >= NN) c = NN - 1;
    int p = atomicAdd(&d_cursor[r], 1);
    d_col[d_rowptr[r] + p] = c;
}

// ---------------- precompute v3 vectors and transposed weights ----------------
__global__ void k_prep(const float* __restrict__ W2, const float* __restrict__ W3,
                       const float* __restrict__ W4, const float* __restrict__ W7) {
    int i = blockIdx.x * blockDim.x + threadIdx.x;
    int stride = gridDim.x * blockDim.x;
    if (i < HOPS * HH) {
        int l = i / HH, hp = i % HH;
        const float* w3 = W3 + l * HH * HH + hp * HH;
        const float* w4 = W4 + l * HH;
        float s = 0.f;
        #pragma unroll 8
        for (int h = 0; h < HH; h++) s += w3[h] * fmaxf(w4[h], 0.f);
        d_v3[i] = s;
    }
    for (int j = i; j < HOPS * HH * HH; j += stride) {
        int l = j / (HH * HH);
        int r = (j / HH) % HH;   // h'
        int c = j % HH;          // k
        d_W2T[l * HH * HH + c * HH + r] = W2[j];
    }
    for (int j = i; j < HH * HH; j += stride) {
        int r = j / HH, c = j % HH;
        d_W7T[c * HH + r] = W7[j];
    }
}

// ---------------- hop 0: node_emb = relu(x*w1 + dw*v3) ----------------
__global__ void k_hop0(const float* __restrict__ x, const float* __restrict__ W1) {
    int i = blockIdx.x * blockDim.x + threadIdx.x;
    if (i >= NN * HH) return;
    int n = i / HH, h = i % HH;
    d_emb_a[i] = fmaxf(x[n] * W1[h] + d_dw[n] * d_v3[h], 0.f);
}

// ---------------- CSR pull gather: aggr[n,:] = sum over in-edges emb[col,:] ----------------
// src: 0 -> d_emb_a, 1 -> d_emb_b
__global__ void __launch_bounds__(256) k_gather(int src) {
    const float4* __restrict__ emb4 =
        (src == 0) ? (const float4*)d_emb_a : (const float4*)d_emb_b;
    int w = (blockIdx.x * blockDim.x + threadIdx.x) >> 5;
    if (w >= NN) return;
    int lane = threadIdx.x & 31;
    int s = d_rowptr[w], e = d_rowptr[w + 1];
    float4 a0 = make_float4(0, 0, 0, 0), a1 = make_float4(0, 0, 0, 0);
    float4 a2 = make_float4(0, 0, 0, 0), a3 = make_float4(0, 0, 0, 0);
    for (int base = s; base < e; base += 32) {
        int myc = (base + lane < e) ? d_col[base + lane] : 0;
        int cnt = min(32, e - base);
        int j = 0;
        for (; j + 3 < cnt; j += 4) {
            int c0 = __shfl_sync(0xffffffffu, myc, j);
            int c1 = __shfl_sync(0xffffffffu, myc, j + 1);
            int c2 = __shfl_sync(0xffffffffu, myc, j + 2);
            int c3 = __shfl_sync(0xffffffffu, myc, j + 3);
            float4 v0 = __ldg(&emb4[c0 * 32 + lane]);
            float4 v1 = __ldg(&emb4[c1 * 32 + lane]);
            float4 v2 = __ldg(&emb4[c2 * 32 + lane]);
            float4 v3 = __ldg(&emb4[c3 * 32 + lane]);
            a0.x += v0.x; a0.y += v0.y; a0.z += v0.z; a0.w += v0.w;
            a1.x += v1.x; a1.y += v1.y; a1.z += v1.z; a1.w += v1.w;
            a2.x += v2.x; a2.y += v2.y; a2.z += v2.z; a2.w += v2.w;
            a3.x += v3.x; a3.y += v3.y; a3.z += v3.z; a3.w += v3.w;
        }
        for (; j < cnt; j++) {
            int c = __shfl_sync(0xffffffffu, myc, j);
            float4 v = __ldg(&emb4[c * 32 + lane]);
            a0.x += v.x; a0.y += v.y; a0.z += v.z; a0.w += v.w;
        }
    }
    float4 acc = make_float4(a0.x + a1.x + a2.x + a3.x,
                             a0.y + a1.y + a2.y + a3.y,
                             a0.z + a1.z + a2.z + a3.z,
                             a0.w + a1.w + a2.w + a3.w);
    ((float4*)d_aggr)[w * 32 + lane] = acc;
}

// ---------------- SGEMM: C[n,h'] = A[n,:] . BT[:,h'] with fused epilogue ----------------
// mode 0 (hop):  A = d_aggr, BT = d_W2T[layer], C = emb(dstSel), epi relu(acc + x*w1 + dw*v3)
// mode 1 (out):  A = d_emb_a, BT = d_W7T, C = d_aggr, raw
#define BM 128
#define BN 128
#define BKK 32
#define TM 8
#define TN 8
__global__ void __launch_bounds__(256) k_gemm(int mode, int layer, int dstSel,
                                              const float* __restrict__ xv,
                                              const float* __restrict__ W1) {
    const float* __restrict__ A  = (mode == 0) ? d_aggr : d_emb_a;
    const float* __restrict__ BT = (mode == 0) ? (d_W2T + layer * HH * HH) : d_W7T;
    float* __restrict__ C = (mode == 0) ? ((dstSel == 0) ? d_emb_a : d_emb_b) : d_aggr;
    const float* w1v = W1 + layer * HH;
    const float* v3v = d_v3 + layer * HH;

    __shared__ float As[BKK][BM];  // transposed A tile
    __shared__ float Bs[BKK][BN];
    int tid = threadIdx.x;
    int m0 = blockIdx.x * BM;
    int tr = tid / 16, tc = tid % 16;
    float acc[TM][TN];
    #pragma unroll
    for (int i = 0; i < TM; i++)
        #pragma unroll
        for (int j = 0; j < TN; j++) acc[i][j] = 0.f;

    for (int kt = 0; kt < HH; kt += BKK) {
        #pragma unroll
        for (int it = 0; it < 4; it++) {
            int r = (tid / 8) + 32 * it;  // 0..127
            int c4 = tid % 8;             // float4 index within 32-wide k slice
            int gr = m0 + r;
            float4 v = make_float4(0, 0, 0, 0);
            if (gr < NN) v = ((const float4*)A)[gr * (HH / 4) + (kt / 4) + c4];
            As[c4 * 4 + 0][r] = v.x;
            As[c4 * 4 + 1][r] = v.y;
            As[c4 * 4 + 2][r] = v.z;
            As[c4 * 4 + 3][r] = v.w;
        }
        #pragma unroll
        for (int it = 0; it < 4; it++) {
            int r = (tid / 32) + 8 * it;  // 0..31
            int c4 = tid % 32;            // 0..31 float4s = 128 floats
            float4 v = ((const float4*)BT)[(kt + r) * (HH / 4) + c4];
            ((float4*)&Bs[r][0])[c4] = v;
        }
        __syncthreads();
        #pragma unroll
        for (int k = 0; k < BKK; k++) {
            float af[TM], bf[TN];
            #pragma unroll
            for (int i = 0; i < TM; i++) af[i] = As[k][tr * TM + i];
            #pragma unroll
            for (int j = 0; j < TN; j++) bf[j] = Bs[k][tc * TN + j];
            #pragma unroll
            for (int i = 0; i < TM; i++)
                #pragma unroll
                for (int j = 0; j < TN; j++) acc[i][j] += af[i] * bf[j];
        }
        __syncthreads();
    }

    #pragma unroll
    for (int i = 0; i < TM; i++) {
        int n = m0 + tr * TM + i;
        if (n >= NN) continue;
        float xn = 0.f, dwn = 0.f;
        if (mode == 0) { xn = xv[n]; dwn = d_dw[n]; }
        #pragma unroll
        for (int j = 0; j < TN; j++) {
            int hp = tc * TN + j;
            float v = acc[i][j];
            if (mode == 0) v = fmaxf(v + xn * w1v[hp] + dwn * v3v[hp], 0.f);
            C[n * HH + hp] = v;
        }
    }
}

// ---------------- pooled[g,:] += node_emb (batch is sorted) ----------------
__global__ void k_pool(const int* __restrict__ batch) {
    int h = threadIdx.x;  // 0..127
    int n0 = blockIdx.x * 512;
    int n1 = min(n0 + 512, NN);
    if (n0 >= NN) return;
    int gcur = batch[n0];
    float acc = 0.f;
    for (int n = n0; n < n1; n++) {
        int g = batch[n];
        if (g != gcur) {
            atomicAdd(&d_pooled[gcur * HH + h], acc);
            acc = 0.f;
            gcur = g;
        }
        acc += d_emb_a[n * HH + h];
    }
    atomicAdd(&d_pooled[gcur * HH + h], acc);
}

// ---------------- per-graph term: t[g] = sum_h' w5a[h'] * relu((pooled @ W6^T)[g,h']) ----------------
__global__ void k_graph(const float* __restrict__ W6, const float* __restrict__ W5) {
    __shared__ float red[GG][HH];
    int hp = threadIdx.x;  // 0..127
    const float* w6 = W6 + hp * HH;
    float w5a = W5[hp];
    for (int g = 0; g < GG; g++) {
        float s = 0.f;
        #pragma unroll 8
        for (int h = 0; h < HH; h++) s += d_pooled[g * HH + h] * w6[h];
        red[g][hp] = fmaxf(s, 0.f) * w5a;
    }
    __syncthreads();
    if (hp < GG) {
        float t = 0.f;
        for (int i = 0; i < HH; i++) t += red[hp][i];
        d_tg[hp] = t;
    }
}

// ---------------- final: out[n] = t[batch[n]] + b5 + sum_h w5b[h]*relu(z[n,h]) ----------------
__global__ void __launch_bounds__(256) k_out(const int* __restrict__ batch,
                                             const float* __restrict__ W5,
                                             const float* __restrict__ b5,
                                             float* __restrict__ out) {
    int w = (blockIdx.x * blockDim.x + threadIdx.x) >> 5;
    if (w >= NN) return;
    int lane = threadIdx.x & 31;
    const float* z = d_aggr + (size_t)w * HH;
    const float* w5b = W5 + HH;
    float s = 0.f;
    #pragma unroll
    for (int j = 0; j < 4; j++) {
        int h = lane + 32 * j;
        s += fmaxf(z[h], 0.f) * w5b[h];
    }
    #pragma unroll
    for (int off = 16; off > 0; off >>= 1) s += __shfl_down_sync(0xffffffffu, s, off);
    if (lane == 0) out[w] = s + d_tg[batch[w]] + b5[0];
}

// ---------------- launch (pure kernel launches; nothing else) ----------------
extern "C" void kernel_launch(void* const* d_in, const int* in_sizes, int n_in,
                              void* d_out, int out_size) {
    const float* x     = (const float*)d_in[0];
    const int*   ei    = (const int*)d_in[1];    // int32 (JAX x64 disabled)
    const float* ea    = (const float*)d_in[2];
    const int*   batch = (const int*)d_in[3];    // int32
    const float* W1    = (const float*)d_in[4];  // [3][128][1]
    const float* W2    = (const float*)d_in[5];  // [3][128][128]
    const float* W3    = (const float*)d_in[6];  // [3][128][128]
    const float* W4    = (const float*)d_in[7];  // [3][128][1]
    const float* W5    = (const float*)d_in[8];  // [1][256]
    const float* b5    = (const float*)d_in[9];  // [1]
    const float* W6    = (const float*)d_in[10]; // [128][128]
    const float* W7    = (const float*)d_in[11]; // [128][128]
    float* out = (float*)d_out;

    const int EB = (EE + 255) / 256;
    const int GB = (NN + BM - 1) / BM;  // 391

    k_zero<<<(NN + 255) / 256, 256>>>();
    k_edge1<<<EB, 256>>>(ei, ea);
    k_scan<<<1, 1024>>>();
    k_edge2<<<EB, 256>>>(ei);
    k_prep<<<64, 256>>>(W2, W3, W4, W7);

    // hop 0 (node_emb starts at zero: no gather, no GEMM)
    k_hop0<<<(NN * HH + 255) / 256, 256>>>(x, W1);

    // hop 1: gather from emb_a -> aggr; gemm -> emb_b
    k_gather<<<(NN * 32 + 255) / 256, 256>>>(0);
    k_gemm<<<GB, 256>>>(0, 1, 1, x, W1);

    // hop 2: gather from emb_b -> aggr; gemm -> emb_a
    k_gather<<<(NN * 32 + 255) / 256, 256>>>(1);
    k_gemm<<<GB, 256>>>(0, 2, 0, x, W1);

    // readout
    k_pool<<<(NN + 511) / 512, 128>>>(batch);
    k_graph<<<1, 128>>>(W6, W5);
    k_gemm<<<GB, 256>>>(1, 0, 0, x, W1);   // z = emb_a @ W7^T -> d_aggr
    k_out<<<(NN * 32 + 255) / 256, 256>>>(batch, W5, b5, out);
}

// round 4
// speedup vs baseline: 1.2052x; 1.2052x over previous
#include <cuda_runtime.h>
#include <cuda_fp16.h>

#define NN 50000
#define EE 1600000
#define GG 16
#define HH 128
#define HOPS 3

// ---------------- scratch (static device memory; no allocations) ----------------
__device__ float  d_emb_a[NN * HH];     // fp32 final-hop embedding (pool + W7 path)
__device__ __half d_emb_h[NN * HH];     // fp16 embedding for the gather path
__device__ float  d_aggr[NN * HH];      // ne_aggr, then reused as z = emb @ W7^T
__device__ float  d_dw[NN];             // sum of edge_attr per destination (row)
__device__ int    d_counts[NN];
__device__ int    d_rowptr[NN + 1];
__device__ int    d_cursor[NN];
__device__ int    d_col[EE];
__device__ float  d_v3[HOPS * HH];       // v3[l][h'] = sum_h W3[l][h',h] * relu(W4[l][h])
__device__ float  d_W2T[HOPS * HH * HH]; // W2T[l][k][h'] = W2[l][h'][k]
__device__ float  d_W7T[HH * HH];        // W7T[k][h'] = W7[h'][k]
__device__ float  d_pooled[GG * HH];
__device__ float  d_tg[GG];

// ---------------- zero accumulators + precompute v3 and transposed weights ----------------
__global__ void k_prep(const float* __restrict__ W2, const float* __restrict__ W3,
                       const float* __restrict__ W4, const float* __restrict__ W7) {
    int i = blockIdx.x * blockDim.x + threadIdx.x;
    int stride = gridDim.x * blockDim.x;
    for (int j = i; j < NN; j += stride) {
        d_dw[j] = 0.f;
        d_counts[j] = 0;
        d_cursor[j] = 0;
    }
    if (i < GG * HH) d_pooled[i] = 0.f;
    if (i < HOPS * HH) {
        int l = i / HH, hp = i % HH;
        const float* w3 = W3 + l * HH * HH + hp * HH;
        const float* w4 = W4 + l * HH;
        float s = 0.f;
        #pragma unroll 8
        for (int h = 0; h < HH; h++) s += w3[h] * fmaxf(w4[h], 0.f);
        d_v3[i] = s;
    }
    for (int j = i; j < HOPS * HH * HH; j += stride) {
        int l = j / (HH * HH);
        int r = (j / HH) % HH;   // h'
        int c = j % HH;          // k
        d_W2T[l * HH * HH + c * HH + r] = W2[j];
    }
    for (int j = i; j < HH * HH; j += stride) {
        int r = j / HH, c = j % HH;
        d_W7T[c * HH + r] = W7[j];
    }
}

// ---------------- edge pass 1: degree histogram + weighted degree ----------------
__global__ void k_edge1(const int* __restrict__ ei, const float* __restrict__ ea) {
    int e = blockIdx.x * blockDim.x + threadIdx.x;
    if (e >= EE) return;
    int r = ei[e];               // row (destination of aggregation)
    if (r < 0 || r >= NN) return;
    atomicAdd(&d_counts[r], 1);
    atomicAdd(&d_dw[r], ea[e]);
}

// ---------------- single-block exclusive scan over counts -> rowptr ----------------
__global__ void k_scan() {
    __shared__ int sm[1024];
    int tid = threadIdx.x;
    const int CH = (NN + 1023) / 1024;  // 49
    int base = tid * CH;
    int s = 0;
    for (int j = 0; j < CH; j++) {
        int idx = base + j;
        if (idx < NN) s += d_counts[idx];
    }
    sm[tid] = s;
    __syncthreads();
    for (int off = 1; off < 1024; off <<= 1) {
        int v = (tid >= off) ? sm[tid - off] : 0;
        __syncthreads();
        sm[tid] += v;
        __syncthreads();
    }
    int run = (tid == 0) ? 0 : sm[tid - 1];
    for (int j = 0; j < CH; j++) {
        int idx = base + j;
        if (idx < NN) {
            d_rowptr[idx] = run;
            run += d_counts[idx];
        }
    }
    if (tid == 1023) d_rowptr[NN] = sm[1023];
}

// ---------------- edge pass 2: scatter cols into CSR ----------------
__global__ void k_edge2(const int* __restrict__ ei) {
    int e = blockIdx.x * blockDim.x + threadIdx.x;
    if (e >= EE) return;
    int r = ei[e];
    int c = ei[EE + e];
    if (r < 0 || r >= NN) return;
    if (c < 0) c = 0;
    if (c >= NN) c = NN - 1;
    int p = atomicAdd(&d_cursor[r], 1);
    d_col[d_rowptr[r] + p] = c;
}

// ---------------- hop 0: emb_h = fp16(relu(x*w1 + dw*v3)) ----------------
__global__ void k_hop0(const float* __restrict__ x, const float* __restrict__ W1) {
    int idx = blockIdx.x * blockDim.x + threadIdx.x;
    if (idx >= NN * 32) return;
    int n = idx >> 5, lane = idx & 31;
    int h0 = lane * 4;
    float xn = x[n], dwn = d_dw[n];
    float v0 = fmaxf(xn * W1[h0 + 0] + dwn * d_v3[h0 + 0], 0.f);
    float v1 = fmaxf(xn * W1[h0 + 1] + dwn * d_v3[h0 + 1], 0.f);
    float v2 = fmaxf(xn * W1[h0 + 2] + dwn * d_v3[h0 + 2], 0.f);
    float v3 = fmaxf(xn * W1[h0 + 3] + dwn * d_v3[h0 + 3], 0.f);
    __half2 p0 = __floats2half2_rn(v0, v1);
    __half2 p1 = __floats2half2_rn(v2, v3);
    uint2 pk;
    pk.x = *(unsigned int*)&p0;
    pk.y = *(unsigned int*)&p1;
    ((uint2*)d_emb_h)[idx] = pk;
}

// ---------------- CSR pull gather (fp16 rows, fp32 accumulate) ----------------
// aggr[n,:] = sum over in-edges emb_h[col,:]
__global__ void __launch_bounds__(256) k_gather() {
    const uint2* __restrict__ emb2 = (const uint2*)d_emb_h;  // 32 uint2 per row
    int w = (blockIdx.x * blockDim.x + threadIdx.x) >> 5;
    if (w >= NN) return;
    int lane = threadIdx.x & 31;
    int s = d_rowptr[w], e = d_rowptr[w + 1];
    float4 a0 = make_float4(0, 0, 0, 0), a1 = make_float4(0, 0, 0, 0);
    float4 a2 = make_float4(0, 0, 0, 0), a3 = make_float4(0, 0, 0, 0);
    for (int base = s; base < e; base += 32) {
        int myc = (base + lane < e) ? d_col[base + lane] : 0;
        int cnt = min(32, e - base);
        int j = 0;
        for (; j + 3 < cnt; j += 4) {
            int c0 = __shfl_sync(0xffffffffu, myc, j);
            int c1 = __shfl_sync(0xffffffffu, myc, j + 1);
            int c2 = __shfl_sync(0xffffffffu, myc, j + 2);
            int c3 = __shfl_sync(0xffffffffu, myc, j + 3);
            uint2 v0 = __ldg(&emb2[c0 * 32 + lane]);
            uint2 v1 = __ldg(&emb2[c1 * 32 + lane]);
            uint2 v2 = __ldg(&emb2[c2 * 32 + lane]);
            uint2 v3 = __ldg(&emb2[c3 * 32 + lane]);
            float2 f;
            f = __half22float2(*(__half2*)&v0.x); a0.x += f.x; a0.y += f.y;
            f = __half22float2(*(__half2*)&v0.y); a0.z += f.x; a0.w += f.y;
            f = __half22float2(*(__half2*)&v1.x); a1.x += f.x; a1.y += f.y;
            f = __half22float2(*(__half2*)&v1.y); a1.z += f.x; a1.w += f.y;
            f = __half22float2(*(__half2*)&v2.x); a2.x += f.x; a2.y += f.y;
            f = __half22float2(*(__half2*)&v2.y); a2.z += f.x; a2.w += f.y;
            f = __half22float2(*(__half2*)&v3.x); a3.x += f.x; a3.y += f.y;
            f = __half22float2(*(__half2*)&v3.y); a3.z += f.x; a3.w += f.y;
        }
        for (; j < cnt; j++) {
            int c = __shfl_sync(0xffffffffu, myc, j);
            uint2 v = __ldg(&emb2[c * 32 + lane]);
            float2 f;
            f = __half22float2(*(__half2*)&v.x); a0.x += f.x; a0.y += f.y;
            f = __half22float2(*(__half2*)&v.y); a0.z += f.x; a0.w += f.y;
        }
    }
    float4 acc = make_float4(a0.x + a1.x + a2.x + a3.x,
                             a0.y + a1.y + a2.y + a3.y,
                             a0.z + a1.z + a2.z + a3.z,
                             a0.w + a1.w + a2.w + a3.w);
    // lane covers h = 4*lane .. 4*lane+3
    ((float4*)d_aggr)[w * 32 + lane] = acc;
}

// ---------------- SGEMM: C[n,h'] = A[n,:] . BT[:,h'] with fused epilogue ----------------
// mode 0 (hop):  A = d_aggr, BT = d_W2T[layer], epi relu(acc + x*w1 + dw*v3);
//                outKind 0 -> fp16 d_emb_h, outKind 1 -> fp32 d_emb_a
// mode 1 (out):  A = d_emb_a, BT = d_W7T, raw fp32 -> d_aggr
#define BM 128
#define BN 128
#define BKK 32
#define TM 8
#define TN 8
__global__ void __launch_bounds__(256) k_gemm(int mode, int layer, int outKind,
                                              const float* __restrict__ xv,
                                              const float* __restrict__ W1) {
    const float* __restrict__ A  = (mode == 0) ? d_aggr : d_emb_a;
    const float* __restrict__ BT = (mode == 0) ? (d_W2T + layer * HH * HH) : d_W7T;
    const float* w1v = W1 + layer * HH;
    const float* v3v = d_v3 + layer * HH;

    __shared__ float As[BKK][BM];  // transposed A tile
    __shared__ float Bs[BKK][BN];
    int tid = threadIdx.x;
    int m0 = blockIdx.x * BM;
    int tr = tid / 16, tc = tid % 16;
    float acc[TM][TN];
    #pragma unroll
    for (int i = 0; i < TM; i++)
        #pragma unroll
        for (int j = 0; j < TN; j++) acc[i][j] = 0.f;

    for (int kt = 0; kt < HH; kt += BKK) {
        #pragma unroll
        for (int it = 0; it < 4; it++) {
            int r = (tid / 8) + 32 * it;  // 0..127
            int c4 = tid % 8;             // float4 index within 32-wide k slice
            int gr = m0 + r;
            float4 v = make_float4(0, 0, 0, 0);
            if (gr < NN) v = ((const float4*)A)[gr * (HH / 4) + (kt / 4) + c4];
            As[c4 * 4 + 0][r] = v.x;
            As[c4 * 4 + 1][r] = v.y;
            As[c4 * 4 + 2][r] = v.z;
            As[c4 * 4 + 3][r] = v.w;
        }
        #pragma unroll
        for (int it = 0; it < 4; it++) {
            int r = (tid / 32) + 8 * it;  // 0..31
            int c4 = tid % 32;            // 0..31 float4s = 128 floats
            float4 v = ((const float4*)BT)[(kt + r) * (HH / 4) + c4];
            ((float4*)&Bs[r][0])[c4] = v;
        }
        __syncthreads();
        #pragma unroll
        for (int k = 0; k < BKK; k++) {
            float af[TM], bf[TN];
            #pragma unroll
            for (int i = 0; i < TM; i++) af[i] = As[k][tr * TM + i];
            #pragma unroll
            for (int j = 0; j < TN; j++) bf[j] = Bs[k][tc * TN + j];
            #pragma unroll
            for (int i = 0; i < TM; i++)
                #pragma unroll
                for (int j = 0; j < TN; j++) acc[i][j] += af[i] * bf[j];
        }
        __syncthreads();
    }

    #pragma unroll
    for (int i = 0; i < TM; i++) {
        int n = m0 + tr * TM + i;
        if (n >= NN) continue;
        if (mode == 0) {
            float xn = xv[n], dwn = d_dw[n];
            float v[TN];
            #pragma unroll
            for (int j = 0; j < TN; j++) {
                int hp = tc * TN + j;
                v[j] = fmaxf(acc[i][j] + xn * w1v[hp] + dwn * v3v[hp], 0.f);
            }
            if (outKind == 0) {
                // fp16 output (gather path)
                #pragma unroll
                for (int j = 0; j < TN; j += 2) {
                    __half2 p = __floats2half2_rn(v[j], v[j + 1]);
                    int hp = tc * TN + j;
                    ((__half2*)d_emb_h)[(n * HH + hp) >> 1] = p;
                }
            } else {
                #pragma unroll
                for (int j = 0; j < TN; j++) d_emb_a[n * HH + tc * TN + j] = v[j];
            }
        } else {
            #pragma unroll
            for (int j = 0; j < TN; j++) d_aggr[n * HH + tc * TN + j] = acc[i][j];
        }
    }
}

// ---------------- pooled[g,:] += node_emb (batch is sorted) ----------------
#define POOL_CHUNK 256
__global__ void k_pool(const int* __restrict__ batch) {
    int h = threadIdx.x;  // 0..127
    int n0 = blockIdx.x * POOL_CHUNK;
    int n1 = min(n0 + POOL_CHUNK, NN);
    if (n0 >= NN) return;
    int gcur = batch[n0];
    float acc = 0.f;
    for (int n = n0; n < n1; n++) {
        int g = batch[n];
        if (g != gcur) {
            atomicAdd(&d_pooled[gcur * HH + h], acc);
            acc = 0.f;
            gcur = g;
        }
        acc += d_emb_a[n * HH + h];
    }
    atomicAdd(&d_pooled[gcur * HH + h], acc);
}

// ---------------- per-graph term: t[g] = sum_h' w5a[h'] * relu((pooled @ W6^T)[g,h']) ----------------
__global__ void k_graph(const float* __restrict__ W6, const float* __restrict__ W5) {
    __shared__ float red[GG][HH];
    int hp = threadIdx.x;  // 0..127
    const float* w6 = W6 + hp * HH;
    float w5a = W5[hp];
    for (int g = 0; g < GG; g++) {
        float s = 0.f;
        #pragma unroll 8
        for (int h = 0; h < HH; h++) s += d_pooled[g * HH + h] * w6[h];
        red[g][hp] = fmaxf(s, 0.f) * w5a;
    }
    __syncthreads();
    if (hp < GG) {
        float t = 0.f;
        for (int i = 0; i < HH; i++) t += red[hp][i];
        d_tg[hp] = t;
    }
}

// ---------------- final: out[n] = t[batch[n]] + b5 + sum_h w5b[h]*relu(z[n,h]) ----------------
__global__ void __launch_bounds__(256) k_out(const int* __restrict__ batch,
                                             const float* __restrict__ W5,
                                             const float* __restrict__ b5,
                                             float* __restrict__ out) {
    int w = (blockIdx.x * blockDim.x + threadIdx.x) >> 5;
    if (w >= NN) return;
    int lane = threadIdx.x & 31;
    const float* z = d_aggr + (size_t)w * HH;
    const float* w5b = W5 + HH;
    float s = 0.f;
    #pragma unroll
    for (int j = 0; j < 4; j++) {
        int h = lane + 32 * j;
        s += fmaxf(z[h], 0.f) * w5b[h];
    }
    #pragma unroll
    for (int off = 16; off > 0; off >>= 1) s += __shfl_down_sync(0xffffffffu, s, off);
    if (lane == 0) out[w] = s + d_tg[batch[w]] + b5[0];
}

// ---------------- launch (pure kernel launches; nothing else) ----------------
extern "C" void kernel_launch(void* const* d_in, const int* in_sizes, int n_in,
                              void* d_out, int out_size) {
    const float* x     = (const float*)d_in[0];
    const int*   ei    = (const int*)d_in[1];    // int32 (JAX x64 disabled)
    const float* ea    = (const float*)d_in[2];
    const int*   batch = (const int*)d_in[3];    // int32
    const float* W1    = (const float*)d_in[4];  // [3][128][1]
    const float* W2    = (const float*)d_in[5];  // [3][128][128]
    const float* W3    = (const float*)d_in[6];  // [3][128][128]
    const float* W4    = (const float*)d_in[7];  // [3][128][1]
    const float* W5    = (const float*)d_in[8];  // [1][256]
    const float* b5    = (const float*)d_in[9];  // [1]
    const float* W6    = (const float*)d_in[10]; // [128][128]
    const float* W7    = (const float*)d_in[11]; // [128][128]
    float* out = (float*)d_out;

    const int EB = (EE + 255) / 256;
    const int GB = (NN + BM - 1) / BM;  // 391

    k_prep<<<64, 256>>>(W2, W3, W4, W7);
    k_edge1<<<EB, 256>>>(ei, ea);
    k_scan<<<1, 1024>>>();
    k_edge2<<<EB, 256>>>(ei);

    // hop 0 (node_emb starts at zero: no gather, no GEMM) -> fp16 emb
    k_hop0<<<(NN * 32 + 255) / 256, 256>>>(x, W1);

    // hop 1: gather fp16 emb -> aggr; gemm -> fp16 emb
    k_gather<<<(NN * 32 + 255) / 256, 256>>>();
    k_gemm<<<GB, 256>>>(0, 1, 0, x, W1);

    // hop 2: gather fp16 emb -> aggr; gemm -> fp32 emb_a
    k_gather<<<(NN * 32 + 255) / 256, 256>>>();
    k_gemm<<<GB, 256>>>(0, 2, 1, x, W1);

    // readout
    k_pool<<<(NN + POOL_CHUNK - 1) / POOL_CHUNK, 128>>>(batch);
    k_graph<<<1, 128>>>(W6, W5);
    k_gemm<<<GB, 256>>>(1, 0, 0, x, W1);   // z = emb_a @ W7^T -> d_aggr
    k_out<<<(NN * 32 + 255) / 256, 256>>>(batch, W5, b5, out);
}

// round 5
// speedup vs baseline: 1.5487x; 1.2850x over previous
#include <cuda_runtime.h>
#include <cuda_fp16.h>

#define NN 50000
#define EE 1600000
#define GG 16
#define HH 128
#define HOPS 3

// ---------------- scratch (static device memory; no allocations) ----------------
__device__ __align__(16) __half d_emb_h[NN * HH];    // fp16 node embedding (gather src, GEMM A, pool src)
__device__ __align__(16) __half d_aggr_h[NN * HH];   // fp16 neighbor aggregation (GEMM A)
__device__ __align__(16) float  d_aggr[NN * HH];     // fp32 z = emb @ W7^T
__device__ float  d_dw[NN];
__device__ int    d_counts[NN];
__device__ int    d_rowptr[NN + 1];
__device__ int    d_cursor[NN];
__device__ int    d_col[EE];
__device__ float  d_v3[HOPS * HH];                    // v3[l][h'] = sum_h W3[l][h',h]*relu(W4[l][h])
__device__ __align__(16) __half d_W2h[HOPS * HH * HH]; // fp16 W2[l][h'][k] (native layout = mma B)
__device__ __align__(16) __half d_W7h[HH * HH];        // fp16 W7[h'][k]
__device__ float  d_pooled[GG * HH];
__device__ float  d_tg[GG];

// ---------------- zero accumulators + precompute v3 + fp16 weights ----------------
__global__ void k_prep(const float* __restrict__ W2, const float* __restrict__ W3,
                       const float* __restrict__ W4, const float* __restrict__ W7) {
    int i = blockIdx.x * blockDim.x + threadIdx.x;
    int stride = gridDim.x * blockDim.x;
    for (int j = i; j < NN; j += stride) {
        d_dw[j] = 0.f;
        d_counts[j] = 0;
        d_cursor[j] = 0;
    }
    if (i < GG * HH) d_pooled[i] = 0.f;
    if (i < HOPS * HH) {
        int l = i / HH, hp = i % HH;
        const float* w3 = W3 + l * HH * HH + hp * HH;
        const float* w4 = W4 + l * HH;
        float s = 0.f;
        #pragma unroll 8
        for (int h = 0; h < HH; h++) s += w3[h] * fmaxf(w4[h], 0.f);
        d_v3[i] = s;
    }
    for (int j = i; j < HOPS * HH * HH; j += stride) d_W2h[j] = __float2half(W2[j]);
    for (int j = i; j < HH * HH; j += stride)        d_W7h[j] = __float2half(W7[j]);
}

// ---------------- edge pass 1: degree histogram + weighted degree ----------------
__global__ void k_edge1(const int* __restrict__ ei, const float* __restrict__ ea) {
    int e = blockIdx.x * blockDim.x + threadIdx.x;
    if (e >= EE) return;
    int r = ei[e];
    if (r < 0 || r >= NN) return;
    atomicAdd(&d_counts[r], 1);
    atomicAdd(&d_dw[r], ea[e]);
}

// ---------------- single-block exclusive scan over counts -> rowptr ----------------
__global__ void k_scan() {
    __shared__ int sm[1024];
    int tid = threadIdx.x;
    const int CH = (NN + 1023) / 1024;  // 49
    int base = tid * CH;
    int s = 0;
    for (int j = 0; j < CH; j++) {
        int idx = base + j;
        if (idx < NN) s += d_counts[idx];
    }
    sm[tid] = s;
    __syncthreads();
    for (int off = 1; off < 1024; off <<= 1) {
        int v = (tid >= off) ? sm[tid - off] : 0;
        __syncthreads();
        sm[tid] += v;
        __syncthreads();
    }
    int run = (tid == 0) ? 0 : sm[tid - 1];
    for (int j = 0; j < CH; j++) {
        int idx = base + j;
        if (idx < NN) {
            d_rowptr[idx] = run;
            run += d_counts[idx];
        }
    }
    if (tid == 1023) d_rowptr[NN] = sm[1023];
}

// ---------------- edge pass 2: scatter cols into CSR ----------------
__global__ void k_edge2(const int* __restrict__ ei) {
    int e = blockIdx.x * blockDim.x + threadIdx.x;
    if (e >= EE) return;
    int r = ei[e];
    int c = ei[EE + e];
    if (r < 0 || r >= NN) return;
    if (c < 0) c = 0;
    if (c >= NN) c = NN - 1;
    int p = atomicAdd(&d_cursor[r], 1);
    d_col[d_rowptr[r] + p] = c;
}

// ---------------- hop 0: emb_h = fp16(relu(x*w1 + dw*v3)) ----------------
__global__ void k_hop0(const float* __restrict__ x, const float* __restrict__ W1) {
    int idx = blockIdx.x * blockDim.x + threadIdx.x;
    if (idx >= NN * 32) return;
    int n = idx >> 5, lane = idx & 31;
    int h0 = lane * 4;
    float xn = x[n], dwn = d_dw[n];
    float v0 = fmaxf(xn * W1[h0 + 0] + dwn * d_v3[h0 + 0], 0.f);
    float v1 = fmaxf(xn * W1[h0 + 1] + dwn * d_v3[h0 + 1], 0.f);
    float v2 = fmaxf(xn * W1[h0 + 2] + dwn * d_v3[h0 + 2], 0.f);
    float v3 = fmaxf(xn * W1[h0 + 3] + dwn * d_v3[h0 + 3], 0.f);
    __half2 p0 = __floats2half2_rn(v0, v1);
    __half2 p1 = __floats2half2_rn(v2, v3);
    uint2 pk;
    pk.x = *(unsigned int*)&p0;
    pk.y = *(unsigned int*)&p1;
    ((uint2*)d_emb_h)[idx] = pk;
}

// ---------------- CSR pull gather (fp16 rows, fp32 accumulate, fp16 out) ----------------
__global__ void __launch_bounds__(256) k_gather() {
    const uint2* __restrict__ emb2 = (const uint2*)d_emb_h;  // 32 uint2 per row
    int w = (blockIdx.x * blockDim.x + threadIdx.x) >> 5;
    if (w >= NN) return;
    int lane = threadIdx.x & 31;
    int s = d_rowptr[w], e = d_rowptr[w + 1];
    float4 a0 = make_float4(0, 0, 0, 0), a1 = make_float4(0, 0, 0, 0);
    float4 a2 = make_float4(0, 0, 0, 0), a3 = make_float4(0, 0, 0, 0);
    for (int base = s; base < e; base += 32) {
        int myc = (base + lane < e) ? d_col[base + lane] : 0;
        int cnt = min(32, e - base);
        int j = 0;
        for (; j + 3 < cnt; j += 4) {
            int c0 = __shfl_sync(0xffffffffu, myc, j);
            int c1 = __shfl_sync(0xffffffffu, myc, j + 1);
            int c2 = __shfl_sync(0xffffffffu, myc, j + 2);
            int c3 = __shfl_sync(0xffffffffu, myc, j + 3);
            uint2 v0 = __ldg(&emb2[c0 * 32 + lane]);
            uint2 v1 = __ldg(&emb2[c1 * 32 + lane]);
            uint2 v2 = __ldg(&emb2[c2 * 32 + lane]);
            uint2 v3 = __ldg(&emb2[c3 * 32 + lane]);
            float2 f;
            f = __half22float2(*(__half2*)&v0.x); a0.x += f.x; a0.y += f.y;
            f = __half22float2(*(__half2*)&v0.y); a0.z += f.x; a0.w += f.y;
            f = __half22float2(*(__half2*)&v1.x); a1.x += f.x; a1.y += f.y;
            f = __half22float2(*(__half2*)&v1.y); a1.z += f.x; a1.w += f.y;
            f = __half22float2(*(__half2*)&v2.x); a2.x += f.x; a2.y += f.y;
            f = __half22float2(*(__half2*)&v2.y); a2.z += f.x; a2.w += f.y;
            f = __half22float2(*(__half2*)&v3.x); a3.x += f.x; a3.y += f.y;
            f = __half22float2(*(__half2*)&v3.y); a3.z += f.x; a3.w += f.y;
        }
        for (; j < cnt; j++) {
            int c = __shfl_sync(0xffffffffu, myc, j);
            uint2 v = __ldg(&emb2[c * 32 + lane]);
            float2 f;
            f = __half22float2(*(__half2*)&v.x); a0.x += f.x; a0.y += f.y;
            f = __half22float2(*(__half2*)&v.y); a0.z += f.x; a0.w += f.y;
        }
    }
    float4 acc = make_float4(a0.x + a1.x + a2.x + a3.x,
                             a0.y + a1.y + a2.y + a3.y,
                             a0.z + a1.z + a2.z + a3.z,
                             a0.w + a1.w + a2.w + a3.w);
    __half2 p0 = __floats2half2_rn(acc.x, acc.y);
    __half2 p1 = __floats2half2_rn(acc.z, acc.w);
    uint2 pk;
    pk.x = *(unsigned int*)&p0;
    pk.y = *(unsigned int*)&p1;
    ((uint2*)d_aggr_h)[w * 32 + lane] = pk;   // h = 4*lane .. 4*lane+3
}

// ---------------- tensor-core GEMM: C[m][n] = sum_k A[m][k] * B[n][k] ----------------
// mode 0: A=d_aggr_h, B=d_W2h[layer];  epi: emb_h[m][n] = fp16(relu(acc + x*w1 + dw*v3))
// mode 1: A=d_emb_h,  B=d_W7h;         epi: d_aggr[m][n] = acc (fp32)
#define KC 64
#define AST 72   // smem row stride in halves (64 + 8 pad; 144B rows, 16B-aligned)
__global__ void __launch_bounds__(256) k_gemm_tc(int mode, int layer,
                                                 const float* __restrict__ xv,
                                                 const float* __restrict__ W1) {
    const __half* __restrict__ Ag = (mode == 0) ? d_aggr_h : d_emb_h;
    const __half* __restrict__ Bg = (mode == 0) ? (d_W2h + layer * HH * HH) : d_W7h;
    __shared__ __half As[128 * AST];
    __shared__ __half Bs[128 * AST];
    int tid = threadIdx.x;
    int m0 = blockIdx.x * 128;
    int wid = tid >> 5, lane = tid & 31;
    int wm = (wid & 1) * 64;    // 2 warps across M (64 rows each)
    int wn = (wid >> 1) * 32;   // 4 warps across N (32 cols each)
    float acc[4][4][4];
    #pragma unroll
    for (int a = 0; a < 4; a++)
        #pragma unroll
        for (int b = 0; b < 4; b++)
            #pragma unroll
            for (int c = 0; c < 4; c++) acc[a][b][c] = 0.f;

    for (int kc = 0; kc < 2; kc++) {
        int kbase = kc * KC;
        #pragma unroll
        for (int it = 0; it < 4; it++) {
            int idx = it * 256 + tid;
            int r = idx >> 3;       // 0..127
            int c = idx & 7;        // uint4 (8 halves) within 64-half row
            int gr = m0 + r; if (gr >= NN) gr = NN - 1;
            *(uint4*)(As + r * AST + c * 8) = *(const uint4*)(Ag + (size_t)gr * HH + kbase + c * 8);
            *(uint4*)(Bs + r * AST + c * 8) = *(const uint4*)(Bg + (size_t)r * HH + kbase + c * 8);
        }
        __syncthreads();
        #pragma unroll
        for (int ks = 0; ks < 4; ks++) {
            int k0 = ks * 16;
            unsigned af[4][4], bf[4][2];
            #pragma unroll
            for (int mt = 0; mt < 4; mt++) {
                int rr = wm + mt * 16 + (lane & 15);
                int cc = k0 + ((lane >> 4) << 3);
                unsigned sa = (unsigned)__cvta_generic_to_shared(As + rr * AST + cc);
                asm volatile("ldmatrix.sync.aligned.m8n8.x4.shared.b16 {%0,%1,%2,%3}, [%4];"
                             : "=r"(af[mt][0]), "=r"(af[mt][1]), "=r"(af[mt][2]), "=r"(af[mt][3])
                             : "r"(sa));
            }
            #pragma unroll
            for (int nt = 0; nt < 4; nt++) {
                int rr = wn + nt * 8 + (lane & 7);
                int cc = k0 + ((lane >> 3) & 1) * 8;
                unsigned sb = (unsigned)__cvta_generic_to_shared(Bs + rr * AST + cc);
                asm volatile("ldmatrix.sync.aligned.m8n8.x2.shared.b16 {%0,%1}, [%2];"
                             : "=r"(bf[nt][0]), "=r"(bf[nt][1]) : "r"(sb));
            }
            #pragma unroll
            for (int mt = 0; mt < 4; mt++)
                #pragma unroll
                for (int nt = 0; nt < 4; nt++)
                    asm volatile("mma.sync.aligned.m16n8k16.row.col.f32.f16.f16.f32 "
                                 "{%0,%1,%2,%3}, {%4,%5,%6,%7}, {%8,%9}, {%0,%1,%2,%3};"
                                 : "+f"(acc[mt][nt][0]), "+f"(acc[mt][nt][1]),
                                   "+f"(acc[mt][nt][2]), "+f"(acc[mt][nt][3])
                                 : "r"(af[mt][0]), "r"(af[mt][1]), "r"(af[mt][2]), "r"(af[mt][3]),
                                   "r"(bf[nt][0]), "r"(bf[nt][1]));
        }
        __syncthreads();
    }

    // epilogue: c-frag m16n8 f32 layout: c0,c1 -> row lane/4, cols 2(lane&3)+{0,1}; c2,c3 -> row+8
    const float* w1v = W1 + layer * HH;
    const float* v3v = d_v3 + layer * HH;
    int rbase = lane >> 2;
    int cpair = (lane & 3) * 2;
    #pragma unroll
    for (int mt = 0; mt < 4; mt++) {
        #pragma unroll
        for (int hh = 0; hh < 2; hh++) {
            int m = m0 + wm + mt * 16 + rbase + hh * 8;
            if (m >= NN) continue;
            if (mode == 0) {
                float xn = xv[m], dwn = d_dw[m];
                #pragma unroll
                for (int nt = 0; nt < 4; nt++) {
                    int n = wn + nt * 8 + cpair;
                    float v0 = fmaxf(acc[mt][nt][hh * 2 + 0] + xn * w1v[n]     + dwn * v3v[n],     0.f);
                    float v1 = fmaxf(acc[mt][nt][hh * 2 + 1] + xn * w1v[n + 1] + dwn * v3v[n + 1], 0.f);
                    *(__half2*)(d_emb_h + (size_t)m * HH + n) = __floats2half2_rn(v0, v1);
                }
            } else {
                #pragma unroll
                for (int nt = 0; nt < 4; nt++) {
                    int n = wn + nt * 8 + cpair;
                    float2 p = make_float2(acc[mt][nt][hh * 2 + 0], acc[mt][nt][hh * 2 + 1]);
                    *(float2*)(d_aggr + (size_t)m * HH + n) = p;
                }
            }
        }
    }
}

// ---------------- pooled[g,:] += emb (fp16 src, fp32 accum; batch sorted) ----------------
#define POOL_CHUNK 256
__global__ void k_pool(const int* __restrict__ batch) {
    int h = threadIdx.x;  // 0..127
    int n0 = blockIdx.x * POOL_CHUNK;
    int n1 = min(n0 + POOL_CHUNK, NN);
    if (n0 >= NN) return;
    int gcur = batch[n0];
    float acc = 0.f;
    for (int n = n0; n < n1; n++) {
        int g = batch[n];
        if (g != gcur) {
            atomicAdd(&d_pooled[gcur * HH + h], acc);
            acc = 0.f;
            gcur = g;
        }
        acc += __half2float(d_emb_h[(size_t)n * HH + h]);
    }
    atomicAdd(&d_pooled[gcur * HH + h], acc);
}

// ---------------- per-graph term: t[g] = sum_h' w5a[h'] * relu((pooled @ W6^T)[g,h']) ----------------
__global__ void k_graph(const float* __restrict__ W6, const float* __restrict__ W5) {
    __shared__ float red[GG][HH];
    int hp = threadIdx.x;  // 0..127
    const float* w6 = W6 + hp * HH;
    float w5a = W5[hp];
    for (int g = 0; g < GG; g++) {
        float s = 0.f;
        #pragma unroll 8
        for (int h = 0; h < HH; h++) s += d_pooled[g * HH + h] * w6[h];
        red[g][hp] = fmaxf(s, 0.f) * w5a;
    }
    __syncthreads();
    if (hp < GG) {
        float t = 0.f;
        for (int i = 0; i < HH; i++) t += red[hp][i];
        d_tg[hp] = t;
    }
}

// ---------------- final: out[n] = t[batch[n]] + b5 + sum_h w5b[h]*relu(z[n,h]) ----------------
__global__ void __launch_bounds__(256) k_out(const int* __restrict__ batch,
                                             const float* __restrict__ W5,
                                             const float* __restrict__ b5,
                                             float* __restrict__ out) {
    int w = (blockIdx.x * blockDim.x + threadIdx.x) >> 5;
    if (w >= NN) return;
    int lane = threadIdx.x & 31;
    const float* z = d_aggr + (size_t)w * HH;
    const float* w5b = W5 + HH;
    float s = 0.f;
    #pragma unroll
    for (int j = 0; j < 4; j++) {
        int h = lane + 32 * j;
        s += fmaxf(z[h], 0.f) * w5b[h];
    }
    #pragma unroll
    for (int off = 16; off > 0; off >>= 1) s += __shfl_down_sync(0xffffffffu, s, off);
    if (lane == 0) out[w] = s + d_tg[batch[w]] + b5[0];
}

// ---------------- launch (pure kernel launches; nothing else) ----------------
extern "C" void kernel_launch(void* const* d_in, const int* in_sizes, int n_in,
                              void* d_out, int out_size) {
    const float* x     = (const float*)d_in[0];
    const int*   ei    = (const int*)d_in[1];    // int32 (JAX x64 disabled)
    const float* ea    = (const float*)d_in[2];
    const int*   batch = (const int*)d_in[3];    // int32
    const float* W1    = (const float*)d_in[4];  // [3][128][1]
    const float* W2    = (const float*)d_in[5];  // [3][128][128]
    const float* W3    = (const float*)d_in[6];  // [3][128][128]
    const float* W4    = (const float*)d_in[7];  // [3][128][1]
    const float* W5    = (const float*)d_in[8];  // [1][256]
    const float* b5    = (const float*)d_in[9];  // [1]
    const float* W6    = (const float*)d_in[10]; // [128][128]
    const float* W7    = (const float*)d_in[11]; // [128][128]
    float* out = (float*)d_out;

    const int EB = (EE + 255) / 256;
    const int GB = (NN + 127) / 128;  // 391

    k_prep<<<64, 256>>>(W2, W3, W4, W7);
    k_edge1<<<EB, 256>>>(ei, ea);
    k_scan<<<1, 1024>>>();
    k_edge2<<<EB, 256>>>(ei);

    // hop 0 (node_emb starts at zero: no gather, no GEMM) -> fp16 emb
    k_hop0<<<(NN * 32 + 255) / 256, 256>>>(x, W1);

    // hop 1: gather fp16 emb -> fp16 aggr; tc-gemm -> fp16 emb
    k_gather<<<(NN * 32 + 255) / 256, 256>>>();
    k_gemm_tc<<<GB, 256>>>(0, 1, x, W1);

    // hop 2
    k_gather<<<(NN * 32 + 255) / 256, 256>>>();
    k_gemm_tc<<<GB, 256>>>(0, 2, x, W1);

    // readout
    k_pool<<<(NN + POOL_CHUNK - 1) / POOL_CHUNK, 128>>>(batch);
    k_graph<<<1, 128>>>(W6, W5);
    k_gemm_tc<<<GB, 256>>>(1, 0, x, W1);   // z = emb @ W7^T -> d_aggr (fp32)
    k_out<<<(NN * 32 + 255) / 256, 256>>>(batch, W5, b5, out);
}

// round 6
// speedup vs baseline: 1.6546x; 1.0684x over previous
#include <cuda_runtime.h>
#include <cuda_fp16.h>

#define NN 50000
#define EE 1600000
#define GG 16
#define HH 128
#define HOPS 3

// ---------------- scratch (static device memory; no allocations) ----------------
__device__ __align__(16) __half d_emb_h[NN * HH];    // fp16 node embedding
__device__ __align__(16) __half d_aggr_h[NN * HH];   // fp16 neighbor aggregation
__device__ float  d_dw[NN];
__device__ int    d_counts[NN];
__device__ int    d_rowptr[NN + 1];
__device__ int    d_cursor[NN];
__device__ int    d_col[EE];
__device__ float  d_v3[HOPS * HH];                     // v3[l][h'] = sum_h W3[l][h',h]*relu(W4[l][h])
__device__ __align__(16) __half d_W2h[HOPS * HH * HH]; // fp16 W2[l][h'][k] (native layout = mma B)
__device__ __align__(16) __half d_W7h[HH * HH];        // fp16 W7[h'][k]
__device__ float  d_pooled[GG * HH];
__device__ float  d_tg[GG];

// ---------------- zero accumulators + precompute v3 + fp16 weights ----------------
__global__ void k_prep(const float* __restrict__ W2, const float* __restrict__ W3,
                       const float* __restrict__ W4, const float* __restrict__ W7) {
    int i = blockIdx.x * blockDim.x + threadIdx.x;
    int stride = gridDim.x * blockDim.x;
    for (int j = i; j < NN; j += stride) {
        d_dw[j] = 0.f;
        d_counts[j] = 0;
        d_cursor[j] = 0;
    }
    if (i < GG * HH) d_pooled[i] = 0.f;
    if (i < HOPS * HH) {
        int l = i / HH, hp = i % HH;
        const float* w3 = W3 + l * HH * HH + hp * HH;
        const float* w4 = W4 + l * HH;
        float s = 0.f;
        #pragma unroll 8
        for (int h = 0; h < HH; h++) s += w3[h] * fmaxf(w4[h], 0.f);
        d_v3[i] = s;
    }
    for (int j = i; j < HOPS * HH * HH; j += stride) d_W2h[j] = __float2half(W2[j]);
    for (int j = i; j < HH * HH; j += stride)        d_W7h[j] = __float2half(W7[j]);
}

// ---------------- edge pass 1: degree histogram + weighted degree ----------------
__global__ void k_edge1(const int* __restrict__ ei, const float* __restrict__ ea) {
    int e = blockIdx.x * blockDim.x + threadIdx.x;
    if (e >= EE) return;
    int r = ei[e];
    if (r < 0 || r >= NN) return;
    atomicAdd(&d_counts[r], 1);
    atomicAdd(&d_dw[r], ea[e]);
}

// ---------------- single-block exclusive scan over counts -> rowptr ----------------
__global__ void k_scan() {
    __shared__ int sm[1024];
    int tid = threadIdx.x;
    const int CH = (NN + 1023) / 1024;  // 49
    int base = tid * CH;
    int s = 0;
    for (int j = 0; j < CH; j++) {
        int idx = base + j;
        if (idx < NN) s += d_counts[idx];
    }
    sm[tid] = s;
    __syncthreads();
    for (int off = 1; off < 1024; off <<= 1) {
        int v = (tid >= off) ? sm[tid - off] : 0;
        __syncthreads();
        sm[tid] += v;
        __syncthreads();
    }
    int run = (tid == 0) ? 0 : sm[tid - 1];
    for (int j = 0; j < CH; j++) {
        int idx = base + j;
        if (idx < NN) {
            d_rowptr[idx] = run;
            run += d_counts[idx];
        }
    }
    if (tid == 1023) d_rowptr[NN] = sm[1023];
}

// ---------------- edge pass 2: scatter cols into CSR ----------------
__global__ void k_edge2(const int* __restrict__ ei) {
    int e = blockIdx.x * blockDim.x + threadIdx.x;
    if (e >= EE) return;
    int r = ei[e];
    int c = ei[EE + e];
    if (r < 0 || r >= NN) return;
    if (c < 0) c = 0;
    if (c >= NN) c = NN - 1;
    int p = atomicAdd(&d_cursor[r], 1);
    d_col[d_rowptr[r] + p] = c;
}

// ---------------- hop 0: emb_h = fp16(relu(x*w1 + dw*v3)) ----------------
__global__ void k_hop0(const float* __restrict__ x, const float* __restrict__ W1) {
    int idx = blockIdx.x * blockDim.x + threadIdx.x;
    if (idx >= NN * 32) return;
    int n = idx >> 5, lane = idx & 31;
    int h0 = lane * 4;
    float xn = x[n], dwn = d_dw[n];
    float v0 = fmaxf(xn * W1[h0 + 0] + dwn * d_v3[h0 + 0], 0.f);
    float v1 = fmaxf(xn * W1[h0 + 1] + dwn * d_v3[h0 + 1], 0.f);
    float v2 = fmaxf(xn * W1[h0 + 2] + dwn * d_v3[h0 + 2], 0.f);
    float v3 = fmaxf(xn * W1[h0 + 3] + dwn * d_v3[h0 + 3], 0.f);
    __half2 p0 = __floats2half2_rn(v0, v1);
    __half2 p1 = __floats2half2_rn(v2, v3);
    uint2 pk;
    pk.x = *(unsigned int*)&p0;
    pk.y = *(unsigned int*)&p1;
    ((uint2*)d_emb_h)[idx] = pk;
}

// ---------------- CSR pull gather: two 16-lane halves, uint4 loads, 8 rows in flight ----------------
#define ACC8(v) do { const __half2* ph = (const __half2*)&(v); float2 f_; \
    f_ = __half22float2(ph[0]); acc[0] += f_.x; acc[1] += f_.y; \
    f_ = __half22float2(ph[1]); acc[2] += f_.x; acc[3] += f_.y; \
    f_ = __half22float2(ph[2]); acc[4] += f_.x; acc[5] += f_.y; \
    f_ = __half22float2(ph[3]); acc[6] += f_.x; acc[7] += f_.y; } while (0)

__global__ void __launch_bounds__(256) k_gather() {
    int w = (blockIdx.x * blockDim.x + threadIdx.x) >> 5;
    if (w >= NN) return;
    int lane = threadIdx.x & 31;
    int half = lane >> 4;   // which neighbor of the pair
    int sub = lane & 15;    // uint4 index within the 256B row (h = sub*8 .. sub*8+7)
    int s = d_rowptr[w], e = d_rowptr[w + 1];
    float acc[8];
    #pragma unroll
    for (int q = 0; q < 8; q++) acc[q] = 0.f;

    for (int base = s; base < e; base += 32) {
        int myc = (base + lane < e) ? d_col[base + lane] : 0;
        int cnt = min(32, e - base);
        int j = 0;
        for (; j + 8 <= cnt; j += 8) {
            int c0 = __shfl_sync(0xffffffffu, myc, j + half);
            int c1 = __shfl_sync(0xffffffffu, myc, j + 2 + half);
            int c2 = __shfl_sync(0xffffffffu, myc, j + 4 + half);
            int c3 = __shfl_sync(0xffffffffu, myc, j + 6 + half);
            uint4 v0 = __ldg((const uint4*)(d_emb_h + (size_t)c0 * HH) + sub);
            uint4 v1 = __ldg((const uint4*)(d_emb_h + (size_t)c1 * HH) + sub);
            uint4 v2 = __ldg((const uint4*)(d_emb_h + (size_t)c2 * HH) + sub);
            uint4 v3 = __ldg((const uint4*)(d_emb_h + (size_t)c3 * HH) + sub);
            ACC8(v0); ACC8(v1); ACC8(v2); ACC8(v3);
        }
        for (; j < cnt; j += 2) {
            int cc = j + half;
            int src = (cc < cnt) ? cc : (cnt - 1);
            int c = __shfl_sync(0xffffffffu, myc, src);
            if (cc < cnt) {
                uint4 v = __ldg((const uint4*)(d_emb_h + (size_t)c * HH) + sub);
                ACC8(v);
            }
        }
    }
    // combine the two halves (lane i += lane i+16), lanes 0-15 write the row
    #pragma unroll
    for (int q = 0; q < 8; q++) acc[q] += __shfl_down_sync(0xffffffffu, acc[q], 16);
    if (half == 0) {
        __half2 p0 = __floats2half2_rn(acc[0], acc[1]);
        __half2 p1 = __floats2half2_rn(acc[2], acc[3]);
        __half2 p2 = __floats2half2_rn(acc[4], acc[5]);
        __half2 p3 = __floats2half2_rn(acc[6], acc[7]);
        uint4 pk;
        pk.x = *(unsigned int*)&p0;
        pk.y = *(unsigned int*)&p1;
        pk.z = *(unsigned int*)&p2;
        pk.w = *(unsigned int*)&p3;
        ((uint4*)d_aggr_h)[w * 16 + sub] = pk;
    }
}

// ---------------- tensor-core GEMM: C[m][n] = sum_k A[m][k] * B[n][k] ----------------
// mode 0: A=d_aggr_h, B=d_W2h[layer];  epi: emb_h[m][n] = fp16(relu(acc + x*w1 + dw*v3))
// mode 1: A=d_emb_h,  B=d_W7h;         epi (fused final): out[m] = tg[batch[m]] + b5 + sum_n w5b[n]*relu(acc)
#define KC 64
#define AST 72   // smem row stride in halves (64 + 8 pad)
__global__ void __launch_bounds__(256) k_gemm_tc(int mode, int layer,
                                                 const float* __restrict__ xv,
                                                 const float* __restrict__ W1,
                                                 const int* __restrict__ batch,
                                                 const float* __restrict__ W5,
                                                 const float* __restrict__ b5,
                                                 float* __restrict__ out) {
    const __half* __restrict__ Ag = (mode == 0) ? d_aggr_h : d_emb_h;
    const __half* __restrict__ Bg = (mode == 0) ? (d_W2h + layer * HH * HH) : d_W7h;
    __shared__ __half As[128 * AST];
    __shared__ __half Bs[128 * AST];
    __shared__ float red[128];
    int tid = threadIdx.x;
    int m0 = blockIdx.x * 128;
    int wid = tid >> 5, lane = tid & 31;
    int wm = (wid & 1) * 64;    // 2 warps across M (64 rows each)
    int wn = (wid >> 1) * 32;   // 4 warps across N (32 cols each)
    if (tid < 128) red[tid] = 0.f;
    float acc[4][4][4];
    #pragma unroll
    for (int a = 0; a < 4; a++)
        #pragma unroll
        for (int b = 0; b < 4; b++)
            #pragma unroll
            for (int c = 0; c < 4; c++) acc[a][b][c] = 0.f;

    for (int kc = 0; kc < 2; kc++) {
        int kbase = kc * KC;
        #pragma unroll
        for (int it = 0; it < 4; it++) {
            int idx = it * 256 + tid;
            int r = idx >> 3;       // 0..127
            int c = idx & 7;        // uint4 (8 halves) within 64-half row
            int gr = m0 + r; if (gr >= NN) gr = NN - 1;
            *(uint4*)(As + r * AST + c * 8) = *(const uint4*)(Ag + (size_t)gr * HH + kbase + c * 8);
            *(uint4*)(Bs + r * AST + c * 8) = *(const uint4*)(Bg + (size_t)r * HH + kbase + c * 8);
        }
        __syncthreads();
        #pragma unroll
        for (int ks = 0; ks < 4; ks++) {
            int k0 = ks * 16;
            unsigned af[4][4], bf[4][2];
            #pragma unroll
            for (int mt = 0; mt < 4; mt++) {
                int rr = wm + mt * 16 + (lane & 15);
                int cc = k0 + ((lane >> 4) << 3);
                unsigned sa = (unsigned)__cvta_generic_to_shared(As + rr * AST + cc);
                asm volatile("ldmatrix.sync.aligned.m8n8.x4.shared.b16 {%0,%1,%2,%3}, [%4];"
                             : "=r"(af[mt][0]), "=r"(af[mt][1]), "=r"(af[mt][2]), "=r"(af[mt][3])
                             : "r"(sa));
            }
            #pragma unroll
            for (int nt = 0; nt < 4; nt++) {
                int rr = wn + nt * 8 + (lane & 7);
                int cc = k0 + ((lane >> 3) & 1) * 8;
                unsigned sb = (unsigned)__cvta_generic_to_shared(Bs + rr * AST + cc);
                asm volatile("ldmatrix.sync.aligned.m8n8.x2.shared.b16 {%0,%1}, [%2];"
                             : "=r"(bf[nt][0]), "=r"(bf[nt][1]) : "r"(sb));
            }
            #pragma unroll
            for (int mt = 0; mt < 4; mt++)
                #pragma unroll
                for (int nt = 0; nt < 4; nt++)
                    asm volatile("mma.sync.aligned.m16n8k16.row.col.f32.f16.f16.f32 "
                                 "{%0,%1,%2,%3}, {%4,%5,%6,%7}, {%8,%9}, {%0,%1,%2,%3};"
                                 : "+f"(acc[mt][nt][0]), "+f"(acc[mt][nt][1]),
                                   "+f"(acc[mt][nt][2]), "+f"(acc[mt][nt][3])
                                 : "r"(af[mt][0]), "r"(af[mt][1]), "r"(af[mt][2]), "r"(af[mt][3]),
                                   "r"(bf[nt][0]), "r"(bf[nt][1]));
        }
        __syncthreads();
    }

    // c-frag m16n8 f32 layout: c0,c1 -> row lane/4, cols 2(lane&3)+{0,1}; c2,c3 -> row+8
    int rbase = lane >> 2;
    int cpair = (lane & 3) * 2;
    if (mode == 0) {
        const float* w1v = W1 + layer * HH;
        const float* v3v = d_v3 + layer * HH;
        #pragma unroll
        for (int mt = 0; mt < 4; mt++) {
            #pragma unroll
            for (int hh = 0; hh < 2; hh++) {
                int m = m0 + wm + mt * 16 + rbase + hh * 8;
                if (m >= NN) continue;
                float xn = xv[m], dwn = d_dw[m];
                #pragma unroll
                for (int nt = 0; nt < 4; nt++) {
                    int n = wn + nt * 8 + cpair;
                    float v0 = fmaxf(acc[mt][nt][hh * 2 + 0] + xn * w1v[n]     + dwn * v3v[n],     0.f);
                    float v1 = fmaxf(acc[mt][nt][hh * 2 + 1] + xn * w1v[n + 1] + dwn * v3v[n + 1], 0.f);
                    *(__half2*)(d_emb_h + (size_t)m * HH + n) = __floats2half2_rn(v0, v1);
                }
            }
        }
    } else {
        // fused final reduction: per row m, sum over n of w5b[n]*relu(acc)
        const float* w5b = W5 + HH;
        #pragma unroll
        for (int mt = 0; mt < 4; mt++) {
            #pragma unroll
            for (int hh = 0; hh < 2; hh++) {
                float s = 0.f;
                #pragma unroll
                for (int nt = 0; nt < 4; nt++) {
                    int n = wn + nt * 8 + cpair;
                    s += fmaxf(acc[mt][nt][hh * 2 + 0], 0.f) * __ldg(w5b + n);
                    s += fmaxf(acc[mt][nt][hh * 2 + 1], 0.f) * __ldg(w5b + n + 1);
                }
                s += __shfl_xor_sync(0xffffffffu, s, 1);
                s += __shfl_xor_sync(0xffffffffu, s, 2);
                if ((lane & 3) == 0)
                    atomicAdd(&red[wm + mt * 16 + rbase + hh * 8], s);
            }
        }
        __syncthreads();
        if (tid < 128) {
            int m = m0 + tid;
            if (m < NN) out[m] = red[tid] + d_tg[batch[m]] + b5[0];
        }
    }
}

// ---------------- pooled[g,:] += emb (fp16 src, fp32 accum; batch sorted) ----------------
#define POOL_CHUNK 256
__global__ void k_pool(const int* __restrict__ batch) {
    int h = threadIdx.x;  // 0..127
    int n0 = blockIdx.x * POOL_CHUNK;
    int n1 = min(n0 + POOL_CHUNK, NN);
    if (n0 >= NN) return;
    int gcur = batch[n0];
    float acc = 0.f;
    for (int n = n0; n < n1; n++) {
        int g = batch[n];
        if (g != gcur) {
            atomicAdd(&d_pooled[gcur * HH + h], acc);
            acc = 0.f;
            gcur = g;
        }
        acc += __half2float(d_emb_h[(size_t)n * HH + h]);
    }
    atomicAdd(&d_pooled[gcur * HH + h], acc);
}

// ---------------- per-graph term: t[g] = sum_h' w5a[h'] * relu((pooled @ W6^T)[g,h']) ----------------
__global__ void k_graph(const float* __restrict__ W6, const float* __restrict__ W5) {
    __shared__ float red[GG][HH];
    int hp = threadIdx.x;  // 0..127
    const float* w6 = W6 + hp * HH;
    float w5a = W5[hp];
    for (int g = 0; g < GG; g++) {
        float s = 0.f;
        #pragma unroll 8
        for (int h = 0; h < HH; h++) s += d_pooled[g * HH + h] * w6[h];
        red[g][hp] = fmaxf(s, 0.f) * w5a;
    }
    __syncthreads();
    if (hp < GG) {
        float t = 0.f;
        for (int i = 0; i < HH; i++) t += red[hp][i];
        d_tg[hp] = t;
    }
}

// ---------------- launch (pure kernel launches; nothing else) ----------------
extern "C" void kernel_launch(void* const* d_in, const int* in_sizes, int n_in,
                              void* d_out, int out_size) {
    const float* x     = (const float*)d_in[0];
    const int*   ei    = (const int*)d_in[1];    // int32 (JAX x64 disabled)
    const float* ea    = (const float*)d_in[2];
    const int*   batch = (const int*)d_in[3];    // int32
    const float* W1    = (const float*)d_in[4];  // [3][128][1]
    const float* W2    = (const float*)d_in[5];  // [3][128][128]
    const float* W3    = (const float*)d_in[6];  // [3][128][128]
    const float* W4    = (const float*)d_in[7];  // [3][128][1]
    const float* W5    = (const float*)d_in[8];  // [1][256]
    const float* b5    = (const float*)d_in[9];  // [1]
    const float* W6    = (const float*)d_in[10]; // [128][128]
    const float* W7    = (const float*)d_in[11]; // [128][128]
    float* out = (float*)d_out;

    const int EB = (EE + 255) / 256;
    const int GB = (NN + 127) / 128;  // 391

    k_prep<<<64, 256>>>(W2, W3, W4, W7);
    k_edge1<<<EB, 256>>>(ei, ea);
    k_scan<<<1, 1024>>>();
    k_edge2<<<EB, 256>>>(ei);

    // hop 0 (node_emb starts at zero: no gather, no GEMM) -> fp16 emb
    k_hop0<<<(NN * 32 + 255) / 256, 256>>>(x, W1);

    // hop 1: gather fp16 emb -> fp16 aggr; tc-gemm -> fp16 emb
    k_gather<<<(NN * 32 + 255) / 256, 256>>>();
    k_gemm_tc<<<GB, 256>>>(0, 1, x, W1, batch, W5, b5, out);

    // hop 2
    k_gather<<<(NN * 32 + 255) / 256, 256>>>();
    k_gemm_tc<<<GB, 256>>>(0, 2, x, W1, batch, W5, b5, out);

    // readout
    k_pool<<<(NN + POOL_CHUNK - 1) / POOL_CHUNK, 128>>>(batch);
    k_graph<<<1, 128>>>(W6, W5);
    k_gemm_tc<<<GB, 256>>>(1, 0, x, W1, batch, W5, b5, out);  // fused: out[n] directly
}